// round 5
// baseline (speedup 1.0000x reference)
#include <cuda_runtime.h>
#include <cstdint>

// ---------------------------------------------------------------------------
// VQ nearest-code quantization + cosine score — 3xTF32 mma.sync + exact refine.
// Inputs : d_in[0]=z [64,256,32,32] f32, d_in[1]=gt same, d_in[2]=codebook [1024,256] f32
// Output : concat( zq[B,H,W,C], cosine[B,W,C], idx_gt[B,H,W], idx[B,H,W] ) as f32
// ---------------------------------------------------------------------------

namespace {
constexpr int kC    = 256;
constexpr int kNE   = 1024;
constexpr int kCHW  = 256 * 1024;
constexpr int kNTok = 64 * 1024;
constexpr int kZQ   = kNTok * kC;
constexpr int kCOS  = 64 * 32 * 256;
constexpr int kOffCos  = kZQ;
constexpr int kOffIdxG = kZQ + kCOS;
constexpr int kOffIdxZ = kOffIdxG + kNTok;
constexpr int kFlagCap = 16384;
}

__device__ float g_codeNorm[kNE];
__device__ float g_tokNorm[2 * kNTok];
__device__ int   g_idx[2 * kNTok];
__device__ float g_blimb[2 * 1024 * 256];
__device__ float g_alimb[4ll * 65536 * 256];   // 256 MiB
__device__ int   g_flagCount;
__device__ int   g_flagList[kFlagCap];

// ------------------------------ helpers ------------------------------------
__device__ __forceinline__ uint32_t smem_u32(const void* p) {
    uint32_t a;
    asm("{ .reg .u64 t; cvta.to.shared.u64 t, %1; cvt.u32.u64 %0, t; }"
        : "=r"(a) : "l"(p));
    return a;
}
__device__ __forceinline__ float to_tf32(float x) {
    float r; asm("cvt.rna.tf32.f32 %0, %1;" : "=f"(r) : "f"(x)); return r;
}
__device__ __forceinline__ void cp16(uint32_t dst, const float* src) {
    asm volatile("cp.async.cg.shared.global [%0], [%1], 16;"
                 :: "r"(dst), "l"(src) : "memory");
}
#define CP_COMMIT() asm volatile("cp.async.commit_group;" ::: "memory")
#define CP_WAIT1()  asm volatile("cp.async.wait_group 1;" ::: "memory")
#define CP_WAIT0()  asm volatile("cp.async.wait_group 0;" ::: "memory")

#define MMA(d, a, b0, b1) \
    asm volatile("mma.sync.aligned.m16n8k8.row.col.f32.tf32.tf32.f32 " \
        "{%0,%1,%2,%3}, {%4,%5,%6,%7}, {%8,%9}, {%0,%1,%2,%3};" \
        : "+f"((d)[0]), "+f"((d)[1]), "+f"((d)[2]), "+f"((d)[3]) \
        : "r"((a)[0]), "r"((a)[1]), "r"((a)[2]), "r"((a)[3]), "r"(b0), "r"(b1))

// SMEM: buffer b at b*110592:
//   Ahi [128][36]f @0, Alo @18432, Bhi [256][36]f @36864, Blo @73728
// norms @221184 (256f), RV @222208, RI @223232, RV2 @224256
#define BUF     110592
#define SM_BH   36864
#define SM_NORM 221184
#define SM_RV   222208
#define SM_RI   223232
#define SM_RV2  224256
#define SMEM_BYTES 225280

// ---------------------------------------------------------------------------
__global__ void code_norm_kernel(const float* __restrict__ cb) {
    int j = blockIdx.x * blockDim.x + threadIdx.x;
    if (j == 0) g_flagCount = 0;          // reset per replay (runs first)
    if (j >= kNE) return;
    const float* r = cb + j * kC;
    float s = 0.f;
    for (int c = 0; c < kC; ++c) s = fmaf(r[c], r[c], s);
    g_codeNorm[j] = s;
}

__global__ void tok_norm_kernel(const float* __restrict__ z,
                                const float* __restrict__ gt) {
    int t = blockIdx.x * blockDim.x + threadIdx.x;
    if (t >= 2 * kNTok) return;
    const float* src = (t < kNTok) ? z : gt;
    int tl = t & (kNTok - 1);
    const float* p = src + (tl >> 10) * kCHW + (tl & 1023);
    float s = 0.f;
    for (int c = 0; c < kC; ++c) { float a = p[c * 1024]; s = fmaf(a, a, s); }
    g_tokNorm[t] = s;
}

__global__ void blimb_kernel(const float* __restrict__ cb) {
    int i = blockIdx.x * blockDim.x + threadIdx.x;   // 65536 float4
    float4 v = ((const float4*)cb)[i];
    float4 hi, lo;
    hi.x = to_tf32(v.x); lo.x = to_tf32(v.x - hi.x);
    hi.y = to_tf32(v.y); lo.y = to_tf32(v.y - hi.y);
    hi.z = to_tf32(v.z); lo.z = to_tf32(v.z - hi.z);
    hi.w = to_tf32(v.w); lo.w = to_tf32(v.w - hi.w);
    ((float4*)g_blimb)[i] = hi;
    ((float4*)g_blimb)[65536 + i] = lo;
}

// transpose+split z/gt: g_alimb[(tensor*2+limb)][tok][k]
__global__ void alimb_kernel(const float* __restrict__ z,
                             const float* __restrict__ gt) {
    __shared__ float s[32][33];
    int blk = blockIdx.x;                 // 2 * 64 * 32 * 8
    int tensor = blk >> 14;
    int b   = (blk >> 8) & 63;
    int hwT = (blk >> 3) & 31;
    int cT  = blk & 7;
    const float* src = tensor ? gt : z;
    int tid = threadIdx.x;
#pragma unroll
    for (int u = 0; u < 4; u++) {
        int cl = (tid >> 5) + u * 8, hw = tid & 31;
        s[cl][hw] = src[b * kCHW + (cT * 32 + cl) * 1024 + hwT * 32 + hw];
    }
    __syncthreads();
    int tokl = tid >> 3, c4 = tid & 7;
    float v0 = s[c4 * 4 + 0][tokl], v1 = s[c4 * 4 + 1][tokl];
    float v2 = s[c4 * 4 + 2][tokl], v3 = s[c4 * 4 + 3][tokl];
    float4 hi, lo;
    hi.x = to_tf32(v0); lo.x = to_tf32(v0 - hi.x);
    hi.y = to_tf32(v1); lo.y = to_tf32(v1 - hi.y);
    hi.z = to_tf32(v2); lo.z = to_tf32(v2 - hi.z);
    hi.w = to_tf32(v3); lo.w = to_tf32(v3 - hi.w);
    size_t base = ((size_t)(tensor * 2) * 65536 + b * 1024 + hwT * 32 + tokl) * 256
                + cT * 32 + c4 * 4;
    *(float4*)(g_alimb + base) = hi;
    *(float4*)(g_alimb + base + 16777216) = lo;
}

// ---------------------------------------------------------------------------
__device__ __forceinline__ void issue_copy(uint32_t sb, int tid, int t,
                                           int tensor, int tloc) {
    const int pass = t >> 3, chunk = t & 7;
    const uint32_t dB = sb + (t & 1) * BUF;
#pragma unroll
    for (int u = 0; u < 8; u++) {                       // A: 2048 f4
        int i = tid + u * 256;
        int limb = i >> 10, r = i & 1023, tok = r >> 3, k4 = r & 7;
        const float* src = g_alimb +
            ((size_t)(tensor * 2 + limb) * 65536 + tloc + tok) * 256 +
            chunk * 32 + k4 * 4;
        cp16(dB + limb * 18432 + tok * 144 + k4 * 16, src);
    }
#pragma unroll
    for (int u = 0; u < 16; u++) {                      // B: 4096 f4
        int i = tid + u * 256;
        int limb = i >> 11, r = i & 2047, code = r >> 3, k4 = r & 7;
        const float* src = g_blimb +
            ((size_t)limb * 1024 + pass * 256 + code) * 256 + chunk * 32 + k4 * 4;
        cp16(dB + SM_BH + limb * 36864 + code * 144 + k4 * 16, src);
    }
}

__global__ void __launch_bounds__(256, 1)
argmin_mma_kernel() {
    extern __shared__ char smem[];
    const uint32_t sb = smem_u32(smem);
    const int tid = threadIdx.x, lane = tid & 31, w = tid >> 5;
    const int r0 = lane >> 2, cg = lane & 3;
    const int mw = w & 3, nw = w >> 2;
    const int tensor = blockIdx.x >> 9;
    const int tloc = (blockIdx.x & 511) * 128;

    float sTok[4];
#pragma unroll
    for (int s = 0; s < 4; s++)
        sTok[s] = g_tokNorm[tensor * kNTok + tloc + mw * 32 + (s >> 1) * 16 + (s & 1) * 8 + r0];

    float rowV = 3.4e38f, rowV2 = 3.4e38f; int rowI = 0;   // per-row top-2 tracker
    float acc[2][16][4];

    issue_copy(sb, tid, 0, tensor, tloc);
    CP_COMMIT();

    for (int t = 0; t < 32; t++) {
        const int pass = t >> 3, chunk = t & 7;
        if (t + 1 < 32) { issue_copy(sb, tid, t + 1, tensor, tloc); CP_COMMIT(); CP_WAIT1(); }
        else CP_WAIT0();
        __syncthreads();
        if (chunk == 0) {
            *(float*)(smem + SM_NORM + tid * 4) = g_codeNorm[pass * 256 + tid];
#pragma unroll
            for (int i = 0; i < 2; i++)
#pragma unroll
                for (int j = 0; j < 16; j++)
#pragma unroll
                    for (int q = 0; q < 4; q++) acc[i][j][q] = 0.f;
        }
        const char* bp = smem + (t & 1) * BUF;
#pragma unroll
        for (int ks = 0; ks < 4; ks++) {
            uint32_t aH[2][4], aL[2][4];
#pragma unroll
            for (int i = 0; i < 2; i++) {
                const char* ab = bp + (mw * 32 + i * 16 + r0) * 144 + (ks * 8 + cg) * 4;
                aH[i][0] = *(const uint32_t*)ab;
                aH[i][1] = *(const uint32_t*)(ab + 8 * 144);
                aH[i][2] = *(const uint32_t*)(ab + 16);
                aH[i][3] = *(const uint32_t*)(ab + 8 * 144 + 16);
                const char* al = ab + 18432;
                aL[i][0] = *(const uint32_t*)al;
                aL[i][1] = *(const uint32_t*)(al + 8 * 144);
                aL[i][2] = *(const uint32_t*)(al + 16);
                aL[i][3] = *(const uint32_t*)(al + 8 * 144 + 16);
            }
#pragma unroll
            for (int j = 0; j < 16; j++) {
                const char* bb = bp + SM_BH + (nw * 128 + j * 8 + r0) * 144 + (ks * 8 + cg) * 4;
                uint32_t bh0 = *(const uint32_t*)bb;
                uint32_t bh1 = *(const uint32_t*)(bb + 16);
                uint32_t bl0 = *(const uint32_t*)(bb + 36864);
                uint32_t bl1 = *(const uint32_t*)(bb + 36864 + 16);
                MMA(acc[0][j], aH[0], bh0, bh1);
                MMA(acc[1][j], aH[1], bh0, bh1);
                MMA(acc[0][j], aH[0], bl0, bl1);
                MMA(acc[1][j], aH[1], bl0, bl1);
                MMA(acc[0][j], aL[0], bh0, bh1);
                MMA(acc[1][j], aL[1], bh0, bh1);
            }
        }
        if (chunk == 7) {
            // per-pass top-2 argmin epilogue
#pragma unroll
            for (int i = 0; i < 2; i++)
#pragma unroll
                for (int p = 0; p < 2; p++) {
                    float v1 = 3.4e38f, v2 = 3.4e38f; int i1 = 0;
#pragma unroll
                    for (int j = 0; j < 16; j++)
#pragma unroll
                        for (int q = 0; q < 2; q++) {
                            int cl = nw * 128 + j * 8 + cg * 2 + q;
                            float n = *(const float*)(smem + SM_NORM + cl * 4);
                            float d = __fadd_rn(__fadd_rn(sTok[i * 2 + p], n),
                                                -__fmul_rn(2.0f, acc[i][j][p * 2 + q]));
                            if (d < v1) { v2 = v1; v1 = d; i1 = cl; }
                            else if (d < v2) v2 = d;
                        }
                    for (int off = 1; off < 4; off <<= 1) {
                        float ov1 = __shfl_xor_sync(0xffffffffu, v1, off);
                        float ov2 = __shfl_xor_sync(0xffffffffu, v2, off);
                        int   oi1 = __shfl_xor_sync(0xffffffffu, i1, off);
                        if (ov1 < v1 || (ov1 == v1 && oi1 < i1)) {
                            v2 = fminf(v1, ov2); v1 = ov1; i1 = oi1;
                        } else {
                            v2 = fminf(v2, ov1);
                        }
                    }
                    if (cg == 0) {
                        int row = mw * 32 + i * 16 + p * 8 + r0;
                        *(float*)(smem + SM_RV  + (nw * 128 + row) * 4) = v1;
                        *(int*)  (smem + SM_RI  + (nw * 128 + row) * 4) = i1;
                        *(float*)(smem + SM_RV2 + (nw * 128 + row) * 4) = v2;
                    }
                }
            __syncthreads();
            if (tid < 128) {
                float a1 = *(float*)(smem + SM_RV + tid * 4);
                int   ai = *(int*)  (smem + SM_RI + tid * 4);
                float a2 = *(float*)(smem + SM_RV2 + tid * 4);
                float b1 = *(float*)(smem + SM_RV + (128 + tid) * 4);
                int   bi = *(int*)  (smem + SM_RI + (128 + tid) * 4);
                float b2 = *(float*)(smem + SM_RV2 + (128 + tid) * 4);
                if (b1 < a1) { a2 = fminf(a1, b2); a1 = b1; ai = bi; }
                else         { a2 = fminf(a2, b1); }
                if (a1 < rowV) { rowV2 = fminf(rowV, a2); rowV = a1; rowI = pass * 256 + ai; }
                else           { rowV2 = fminf(rowV2, a1); }
            }
        }
        __syncthreads();
    }
    if (tid < 128) {
        int t = tensor * kNTok + tloc + tid;
        g_idx[t] = rowI;
        if (rowV2 - rowV < 1e-3f) {          // near-tie: queue exact re-check
            int slot = atomicAdd(&g_flagCount, 1);
            if (slot < kFlagCap) g_flagList[slot] = t;
        }
    }
}

// ---------------------------------------------------------------------------
// Exact re-check for flagged tokens: bit-identical to the R1 scalar chain.
__global__ void __launch_bounds__(256)
refine_kernel(const float* __restrict__ z, const float* __restrict__ gt,
              const float* __restrict__ cb) {
    __shared__ float x[256];
    __shared__ float rv[256];
    __shared__ int   ri[256];
    int nf = g_flagCount; if (nf > kFlagCap) nf = kFlagCap;
    int tid = threadIdx.x;
    for (int f = blockIdx.x; f < nf; f += gridDim.x) {
        int t = g_flagList[f];
        int tensor = t >> 16, tl = t & 65535;
        const float* src = tensor ? gt : z;
        __syncthreads();
        x[tid] = src[(tl >> 10) * kCHW + tid * 1024 + (tl & 1023)];
        __syncthreads();
        float s = g_tokNorm[t];
        float best = 3.4e38f; int bi = 0;
        for (int j0 = 0; j0 < 4; j0++) {
            int code = tid * 4 + j0;
            const float* e = cb + code * 256;
            float acc = 0.f;
#pragma unroll 16
            for (int k = 0; k < 256; k++) acc = fmaf(x[k], e[k], acc);
            float d = __fadd_rn(__fadd_rn(s, g_codeNorm[code]),
                                -__fmul_rn(2.0f, acc));
            if (d < best) { best = d; bi = code; }
        }
        rv[tid] = best; ri[tid] = bi;
        __syncthreads();
        for (int off = 128; off > 0; off >>= 1) {
            if (tid < off) {
                float ov = rv[tid + off]; int oi = ri[tid + off];
                if (ov < rv[tid] || (ov == rv[tid] && oi < ri[tid])) {
                    rv[tid] = ov; ri[tid] = oi;
                }
            }
            __syncthreads();
        }
        if (tid == 0) g_idx[t] = ri[0];
    }
}

// ---------------------------------------------------------------------------
__global__ void write_zq_kernel(const float* __restrict__ cb,
                                float* __restrict__ out) {
    int i = blockIdx.x * blockDim.x + threadIdx.x;
    int t = i >> 6, cq = i & 63;
    int idx = g_idx[t];
    ((float4*)out)[i] = ((const float4*)(cb + idx * kC))[cq];
}

__global__ void write_idx_kernel(float* __restrict__ out) {
    int t = blockIdx.x * blockDim.x + threadIdx.x;
    if (t >= kNTok) return;
    out[kOffIdxG + t] = (float)g_idx[kNTok + t];
    out[kOffIdxZ + t] = (float)g_idx[t];
}

__global__ void cosine_kernel(const float* __restrict__ cb,
                              float* __restrict__ out) {
    int bw = blockIdx.x;
    int b = bw >> 5, w = bw & 31;
    int c = threadIdx.x;
    __shared__ int sig[32], siz[32];
    if (threadIdx.x < 32) {
        int h = threadIdx.x;
        int t = b * 1024 + h * 32 + w;
        sig[h] = g_idx[kNTok + t];
        siz[h] = g_idx[t];
    }
    __syncthreads();
    float num = 0.f, ng = 0.f, nz = 0.f;
    for (int h = 0; h < 32; ++h) {
        float g = cb[sig[h] * kC + c];
        float q = cb[siz[h] * kC + c];
        num = fmaf(g, q, num);
        ng  = fmaf(g, g, ng);
        nz  = fmaf(q, q, nz);
    }
    float den = fmaxf(sqrtf(ng), 1e-8f) * fmaxf(sqrtf(nz), 1e-8f);
    out[kOffCos + bw * kC + c] = num / den;
}

// ---------------------------------------------------------------------------
extern "C" void kernel_launch(void* const* d_in, const int* in_sizes, int n_in,
                              void* d_out, int out_size) {
    const float* z  = (const float*)d_in[0];
    const float* gt = (const float*)d_in[1];
    const float* cb = (const float*)d_in[2];
    float* out = (float*)d_out;
    (void)in_sizes; (void)n_in; (void)out_size;

    cudaFuncSetAttribute(argmin_mma_kernel,
                         cudaFuncAttributeMaxDynamicSharedMemorySize, SMEM_BYTES);

    code_norm_kernel<<<4, 256>>>(cb);
    tok_norm_kernel<<<(2 * kNTok + 255) / 256, 256>>>(z, gt);
    blimb_kernel<<<256, 256>>>(cb);
    alimb_kernel<<<32768, 256>>>(z, gt);
    argmin_mma_kernel<<<1024, 256, SMEM_BYTES>>>();
    refine_kernel<<<4096, 256>>>(z, gt, cb);
    write_zq_kernel<<<(kZQ / 4) / 256, 256>>>(cb, out);
    write_idx_kernel<<<(kNTok + 255) / 256, 256>>>(out);
    cosine_kernel<<<64 * 32, 256>>>(cb, out);
}

// round 6
// speedup vs baseline: 1.0275x; 1.0275x over previous
#include <cuda_runtime.h>
#include <cstdint>

// ---------------------------------------------------------------------------
// VQ nearest-code quantization + cosine score — 1xTF32 mma.sync + exact refine.
// Inputs : d_in[0]=z [64,256,32,32] f32, d_in[1]=gt same, d_in[2]=codebook [1024,256] f32
// Output : concat( zq[B,H,W,C], cosine[B,W,C], idx_gt[B,H,W], idx[B,H,W] ) as f32
// ---------------------------------------------------------------------------

namespace {
constexpr int kC    = 256;
constexpr int kNE   = 1024;
constexpr int kCHW  = 256 * 1024;
constexpr int kNTok = 64 * 1024;
constexpr int kZQ   = kNTok * kC;
constexpr int kCOS  = 64 * 32 * 256;
constexpr int kOffCos  = kZQ;
constexpr int kOffIdxG = kZQ + kCOS;
constexpr int kOffIdxZ = kOffIdxG + kNTok;
constexpr int kFlagCap = 2 * kNTok;       // cannot overflow: correctness never depends on estimate
constexpr float kMargin = 2e-3f;          // ~8 sigma of tf32 dot error
}

__device__ float g_codeNorm[kNE];
__device__ float g_tokNorm[2 * kNTok];
__device__ int   g_idx[2 * kNTok];
__device__ float g_blimb[1024 * 256];             // tf32-rounded codebook
__device__ float g_alimb[2ll * 65536 * 256];      // tf32-rounded tokens, token-major (128 MiB)
__device__ int   g_flagCount;
__device__ int   g_flagList[kFlagCap];

// ------------------------------ helpers ------------------------------------
__device__ __forceinline__ uint32_t smem_u32(const void* p) {
    uint32_t a;
    asm("{ .reg .u64 t; cvta.to.shared.u64 t, %1; cvt.u32.u64 %0, t; }"
        : "=r"(a) : "l"(p));
    return a;
}
__device__ __forceinline__ float to_tf32(float x) {
    float r; asm("cvt.rna.tf32.f32 %0, %1;" : "=f"(r) : "f"(x)); return r;
}
__device__ __forceinline__ void cp16(uint32_t dst, const float* src) {
    asm volatile("cp.async.cg.shared.global [%0], [%1], 16;"
                 :: "r"(dst), "l"(src) : "memory");
}
#define CP_COMMIT() asm volatile("cp.async.commit_group;" ::: "memory")
#define CP_WAIT1()  asm volatile("cp.async.wait_group 1;" ::: "memory")
#define CP_WAIT0()  asm volatile("cp.async.wait_group 0;" ::: "memory")

#define MMA(d, a, b0, b1) \
    asm volatile("mma.sync.aligned.m16n8k8.row.col.f32.tf32.tf32.f32 " \
        "{%0,%1,%2,%3}, {%4,%5,%6,%7}, {%8,%9}, {%0,%1,%2,%3};" \
        : "+f"((d)[0]), "+f"((d)[1]), "+f"((d)[2]), "+f"((d)[3]) \
        : "r"((a)[0]), "r"((a)[1]), "r"((a)[2]), "r"((a)[3]), "r"(b0), "r"(b1))

// SMEM: buffer b at b*55296: A [128][36]f @0, B [256][36]f @18432
// norms @110592 (256f), RV @111616, RI @112640, RV2 @113664
#define BUF     55296
#define SM_B    18432
#define SM_NORM 110592
#define SM_RV   111616
#define SM_RI   112640
#define SM_RV2  113664
#define SMEM_BYTES 114688

// ---------------------------------------------------------------------------
__global__ void code_norm_kernel(const float* __restrict__ cb) {
    int j = blockIdx.x * blockDim.x + threadIdx.x;
    if (j == 0) g_flagCount = 0;          // reset per replay (runs first)
    if (j >= kNE) return;
    const float* r = cb + j * kC;
    float s = 0.f;
    for (int c = 0; c < kC; ++c) s = fmaf(r[c], r[c], s);
    g_codeNorm[j] = s;
}

__global__ void tok_norm_kernel(const float* __restrict__ z,
                                const float* __restrict__ gt) {
    int t = blockIdx.x * blockDim.x + threadIdx.x;
    if (t >= 2 * kNTok) return;
    const float* src = (t < kNTok) ? z : gt;
    int tl = t & (kNTok - 1);
    const float* p = src + (tl >> 10) * kCHW + (tl & 1023);
    float s = 0.f;
    for (int c = 0; c < kC; ++c) { float a = p[c * 1024]; s = fmaf(a, a, s); }
    g_tokNorm[t] = s;
}

__global__ void blimb_kernel(const float* __restrict__ cb) {
    int i = blockIdx.x * blockDim.x + threadIdx.x;   // 65536 float4
    float4 v = ((const float4*)cb)[i];
    float4 hi;
    hi.x = to_tf32(v.x); hi.y = to_tf32(v.y);
    hi.z = to_tf32(v.z); hi.w = to_tf32(v.w);
    ((float4*)g_blimb)[i] = hi;
}

// transpose+round z/gt: g_alimb[tensor][tok][k]
__global__ void alimb_kernel(const float* __restrict__ z,
                             const float* __restrict__ gt) {
    __shared__ float s[32][33];
    int blk = blockIdx.x;                 // 2 * 64 * 32 * 8
    int tensor = blk >> 14;
    int b   = (blk >> 8) & 63;
    int hwT = (blk >> 3) & 31;
    int cT  = blk & 7;
    const float* src = tensor ? gt : z;
    int tid = threadIdx.x;
#pragma unroll
    for (int u = 0; u < 4; u++) {
        int cl = (tid >> 5) + u * 8, hw = tid & 31;
        s[cl][hw] = src[b * kCHW + (cT * 32 + cl) * 1024 + hwT * 32 + hw];
    }
    __syncthreads();
    int tokl = tid >> 3, c4 = tid & 7;
    float4 hi;
    hi.x = to_tf32(s[c4 * 4 + 0][tokl]);
    hi.y = to_tf32(s[c4 * 4 + 1][tokl]);
    hi.z = to_tf32(s[c4 * 4 + 2][tokl]);
    hi.w = to_tf32(s[c4 * 4 + 3][tokl]);
    size_t base = ((size_t)tensor * 65536 + b * 1024 + hwT * 32 + tokl) * 256
                + cT * 32 + c4 * 4;
    *(float4*)(g_alimb + base) = hi;
}

// ---------------------------------------------------------------------------
__device__ __forceinline__ void issue_copy(uint32_t sb, int tid, int t,
                                           int tensor, int tloc) {
    const int pass = t >> 3, chunk = t & 7;
    const uint32_t dB = sb + (t & 1) * BUF;
#pragma unroll
    for (int u = 0; u < 4; u++) {                       // A: 1024 f4
        int i = tid + u * 256;
        int tok = i >> 3, k4 = i & 7;
        const float* src = g_alimb +
            ((size_t)tensor * 65536 + tloc + tok) * 256 + chunk * 32 + k4 * 4;
        cp16(dB + tok * 144 + k4 * 16, src);
    }
#pragma unroll
    for (int u = 0; u < 8; u++) {                       // B: 2048 f4
        int i = tid + u * 256;
        int code = i >> 3, k4 = i & 7;
        const float* src = g_blimb +
            ((size_t)(pass * 256 + code)) * 256 + chunk * 32 + k4 * 4;
        cp16(dB + SM_B + code * 144 + k4 * 16, src);
    }
}

__global__ void __launch_bounds__(256, 1)
argmin_mma_kernel() {
    extern __shared__ char smem[];
    const uint32_t sb = smem_u32(smem);
    const int tid = threadIdx.x, lane = tid & 31, w = tid >> 5;
    const int r0 = lane >> 2, cg = lane & 3;
    const int mw = w & 3, nw = w >> 2;
    const int tensor = blockIdx.x >> 9;
    const int tloc = (blockIdx.x & 511) * 128;

    float sTok[4];
#pragma unroll
    for (int s = 0; s < 4; s++)
        sTok[s] = g_tokNorm[tensor * kNTok + tloc + mw * 32 + (s >> 1) * 16 + (s & 1) * 8 + r0];

    float rowV = 3.4e38f, rowV2 = 3.4e38f; int rowI = 0;   // per-row top-2 tracker
    float acc[2][16][4];

    issue_copy(sb, tid, 0, tensor, tloc);
    CP_COMMIT();

    for (int t = 0; t < 32; t++) {
        const int pass = t >> 3, chunk = t & 7;
        if (t + 1 < 32) { issue_copy(sb, tid, t + 1, tensor, tloc); CP_COMMIT(); CP_WAIT1(); }
        else CP_WAIT0();
        __syncthreads();
        if (chunk == 0) {
            *(float*)(smem + SM_NORM + tid * 4) = g_codeNorm[pass * 256 + tid];
#pragma unroll
            for (int i = 0; i < 2; i++)
#pragma unroll
                for (int j = 0; j < 16; j++)
#pragma unroll
                    for (int q = 0; q < 4; q++) acc[i][j][q] = 0.f;
        }
        const char* bp = smem + (t & 1) * BUF;
#pragma unroll
        for (int ks = 0; ks < 4; ks++) {
            uint32_t aH[2][4];
#pragma unroll
            for (int i = 0; i < 2; i++) {
                const char* ab = bp + (mw * 32 + i * 16 + r0) * 144 + (ks * 8 + cg) * 4;
                aH[i][0] = *(const uint32_t*)ab;
                aH[i][1] = *(const uint32_t*)(ab + 8 * 144);
                aH[i][2] = *(const uint32_t*)(ab + 16);
                aH[i][3] = *(const uint32_t*)(ab + 8 * 144 + 16);
            }
#pragma unroll
            for (int j = 0; j < 16; j++) {
                const char* bb = bp + SM_B + (nw * 128 + j * 8 + r0) * 144 + (ks * 8 + cg) * 4;
                uint32_t bh0 = *(const uint32_t*)bb;
                uint32_t bh1 = *(const uint32_t*)(bb + 16);
                MMA(acc[0][j], aH[0], bh0, bh1);
                MMA(acc[1][j], aH[1], bh0, bh1);
            }
        }
        if (chunk == 7) {
            // per-pass top-2 argmin epilogue
#pragma unroll
            for (int i = 0; i < 2; i++)
#pragma unroll
                for (int p = 0; p < 2; p++) {
                    float v1 = 3.4e38f, v2 = 3.4e38f; int i1 = 0;
#pragma unroll
                    for (int j = 0; j < 16; j++)
#pragma unroll
                        for (int q = 0; q < 2; q++) {
                            int cl = nw * 128 + j * 8 + cg * 2 + q;
                            float n = *(const float*)(smem + SM_NORM + cl * 4);
                            float d = __fadd_rn(__fadd_rn(sTok[i * 2 + p], n),
                                                -__fmul_rn(2.0f, acc[i][j][p * 2 + q]));
                            if (d < v1) { v2 = v1; v1 = d; i1 = cl; }
                            else if (d < v2) v2 = d;
                        }
                    for (int off = 1; off < 4; off <<= 1) {
                        float ov1 = __shfl_xor_sync(0xffffffffu, v1, off);
                        float ov2 = __shfl_xor_sync(0xffffffffu, v2, off);
                        int   oi1 = __shfl_xor_sync(0xffffffffu, i1, off);
                        if (ov1 < v1 || (ov1 == v1 && oi1 < i1)) {
                            v2 = fminf(v1, ov2); v1 = ov1; i1 = oi1;
                        } else {
                            v2 = fminf(v2, ov1);
                        }
                    }
                    if (cg == 0) {
                        int row = mw * 32 + i * 16 + p * 8 + r0;
                        *(float*)(smem + SM_RV  + (nw * 128 + row) * 4) = v1;
                        *(int*)  (smem + SM_RI  + (nw * 128 + row) * 4) = i1;
                        *(float*)(smem + SM_RV2 + (nw * 128 + row) * 4) = v2;
                    }
                }
            __syncthreads();
            if (tid < 128) {
                float a1 = *(float*)(smem + SM_RV + tid * 4);
                int   ai = *(int*)  (smem + SM_RI + tid * 4);
                float a2 = *(float*)(smem + SM_RV2 + tid * 4);
                float b1 = *(float*)(smem + SM_RV + (128 + tid) * 4);
                int   bi = *(int*)  (smem + SM_RI + (128 + tid) * 4);
                float b2 = *(float*)(smem + SM_RV2 + (128 + tid) * 4);
                if (b1 < a1) { a2 = fminf(a1, b2); a1 = b1; ai = bi; }
                else         { a2 = fminf(a2, b1); }
                if (a1 < rowV) { rowV2 = fminf(rowV, a2); rowV = a1; rowI = pass * 256 + ai; }
                else           { rowV2 = fminf(rowV2, a1); }
            }
        }
        __syncthreads();
    }
    if (tid < 128) {
        int t = tensor * kNTok + tloc + tid;
        g_idx[t] = rowI;
        if (rowV2 - rowV < kMargin) {        // near-tie: queue exact re-check
            int slot = atomicAdd(&g_flagCount, 1);
            if (slot < kFlagCap) g_flagList[slot] = t;
        }
    }
}

// ---------------------------------------------------------------------------
// Exact re-check for flagged tokens: bit-identical to the R1 scalar chain.
__global__ void __launch_bounds__(256)
refine_kernel(const float* __restrict__ z, const float* __restrict__ gt,
              const float* __restrict__ cb) {
    __shared__ float x[256];
    __shared__ float rv[256];
    __shared__ int   ri[256];
    int nf = g_flagCount; if (nf > kFlagCap) nf = kFlagCap;
    int tid = threadIdx.x;
    for (int f = blockIdx.x; f < nf; f += gridDim.x) {
        int t = g_flagList[f];
        int tensor = t >> 16, tl = t & 65535;
        const float* src = tensor ? gt : z;
        __syncthreads();
        x[tid] = src[(tl >> 10) * kCHW + tid * 1024 + (tl & 1023)];
        __syncthreads();
        float s = g_tokNorm[t];
        float best = 3.4e38f; int bi = 0;
        for (int j0 = 0; j0 < 4; j0++) {
            int code = tid * 4 + j0;
            const float* e = cb + code * 256;
            float acc = 0.f;
#pragma unroll 16
            for (int k = 0; k < 256; k++) acc = fmaf(x[k], e[k], acc);
            float d = __fadd_rn(__fadd_rn(s, g_codeNorm[code]),
                                -__fmul_rn(2.0f, acc));
            if (d < best) { best = d; bi = code; }
        }
        rv[tid] = best; ri[tid] = bi;
        __syncthreads();
        for (int off = 128; off > 0; off >>= 1) {
            if (tid < off) {
                float ov = rv[tid + off]; int oi = ri[tid + off];
                if (ov < rv[tid] || (ov == rv[tid] && oi < ri[tid])) {
                    rv[tid] = ov; ri[tid] = oi;
                }
            }
            __syncthreads();
        }
        if (tid == 0) g_idx[t] = ri[0];
    }
}

// ---------------------------------------------------------------------------
__global__ void write_zq_kernel(const float* __restrict__ cb,
                                float* __restrict__ out) {
    int i = blockIdx.x * blockDim.x + threadIdx.x;
    int t = i >> 6, cq = i & 63;
    int idx = g_idx[t];
    ((float4*)out)[i] = ((const float4*)(cb + idx * kC))[cq];
}

__global__ void write_idx_kernel(float* __restrict__ out) {
    int t = blockIdx.x * blockDim.x + threadIdx.x;
    if (t >= kNTok) return;
    out[kOffIdxG + t] = (float)g_idx[kNTok + t];
    out[kOffIdxZ + t] = (float)g_idx[t];
}

__global__ void cosine_kernel(const float* __restrict__ cb,
                              float* __restrict__ out) {
    int bw = blockIdx.x;
    int b = bw >> 5, w = bw & 31;
    int c = threadIdx.x;
    __shared__ int sig[32], siz[32];
    if (threadIdx.x < 32) {
        int h = threadIdx.x;
        int t = b * 1024 + h * 32 + w;
        sig[h] = g_idx[kNTok + t];
        siz[h] = g_idx[t];
    }
    __syncthreads();
    float num = 0.f, ng = 0.f, nz = 0.f;
    for (int h = 0; h < 32; ++h) {
        float g = cb[sig[h] * kC + c];
        float q = cb[siz[h] * kC + c];
        num = fmaf(g, q, num);
        ng  = fmaf(g, g, ng);
        nz  = fmaf(q, q, nz);
    }
    float den = fmaxf(sqrtf(ng), 1e-8f) * fmaxf(sqrtf(nz), 1e-8f);
    out[kOffCos + bw * kC + c] = num / den;
}

// ---------------------------------------------------------------------------
extern "C" void kernel_launch(void* const* d_in, const int* in_sizes, int n_in,
                              void* d_out, int out_size) {
    const float* z  = (const float*)d_in[0];
    const float* gt = (const float*)d_in[1];
    const float* cb = (const float*)d_in[2];
    float* out = (float*)d_out;
    (void)in_sizes; (void)n_in; (void)out_size;

    cudaFuncSetAttribute(argmin_mma_kernel,
                         cudaFuncAttributeMaxDynamicSharedMemorySize, SMEM_BYTES);

    code_norm_kernel<<<4, 256>>>(cb);
    tok_norm_kernel<<<(2 * kNTok + 255) / 256, 256>>>(z, gt);
    blimb_kernel<<<256, 256>>>(cb);
    alimb_kernel<<<32768, 256>>>(z, gt);
    argmin_mma_kernel<<<1024, 256, SMEM_BYTES>>>();
    refine_kernel<<<4096, 256>>>(z, gt, cb);
    write_zq_kernel<<<(kZQ / 4) / 256, 256>>>(cb, out);
    write_idx_kernel<<<(kNTok + 255) / 256, 256>>>(out);
    cosine_kernel<<<64 * 32, 256>>>(cb, out);
}